// round 14
// baseline (speedup 1.0000x reference)
#include <cuda_runtime.h>
#include <cuda_bf16.h>
#include <cstdint>

#define B_ROWS 16384
#define C_ROWS 4096
#define DDIM   1024

// GEMM tiling
#define TM 128            // CTA M
#define TN 128            // CTA N
#define TK 64             // K chunk (per pipeline stage)
#define NSTAGE 3
#define KCHUNKS (DDIM / TK)        // 16
#define K16S (TK / 16)             // 4 mma k-steps per chunk

#define A_STAGE_BYTES (TM * TK * 2)            // 16384
#define B_STAGE_BYTES (TN * TK * 2)            // 16384
#define STAGE_BYTES (A_STAGE_BYTES + B_STAGE_BYTES)   // 32768
#define SMEM_DYN (1024 + NSTAGE * STAGE_BYTES)        // 99328  -> 2 CTAs/SM

// ---- device scratch (allocation-free rule: __device__ globals) ----
__device__ __align__(16) __nv_bfloat16 g_feat_bf16[B_ROWS * DDIM];   // 32 MB
__device__ __align__(16) __nv_bfloat16 g_cent_bf16[C_ROWS * DDIM];   // 8 MB
__device__ float g_x2[B_ROWS];
__device__ float g_c2[C_ROWS];

// ============================ PTX helpers (baseline PTX only) ============================
__device__ __forceinline__ uint32_t smem_u32(const void* p) {
    return (uint32_t)__cvta_generic_to_shared(p);
}

#define CP_ASYNC16(smem_addr, gptr) \
    asm volatile("cp.async.cg.shared.global [%0], [%1], 16;" \
                 :: "r"((uint32_t)(smem_addr)), "l"(gptr) : "memory")

#define CP_ASYNC_COMMIT() asm volatile("cp.async.commit_group;" ::: "memory")
#define CP_ASYNC_WAIT1()  asm volatile("cp.async.wait_group 1;" ::: "memory")
#define CP_ASYNC_WAIT0()  asm volatile("cp.async.wait_group 0;" ::: "memory")

#define LDSM_X4(r, addr) \
    asm volatile("ldmatrix.sync.aligned.m8n8.x4.shared.b16 {%0,%1,%2,%3}, [%4];" \
                 : "=r"((r)[0]), "=r"((r)[1]), "=r"((r)[2]), "=r"((r)[3]) \
                 : "r"((uint32_t)(addr)))

#define MMA_BF16(d, a, b0, b1) \
    asm volatile("mma.sync.aligned.m16n8k16.row.col.f32.bf16.bf16.f32 " \
                 "{%0,%1,%2,%3}, {%4,%5,%6,%7}, {%8,%9}, {%0,%1,%2,%3};" \
                 : "+f"((d)[0]), "+f"((d)[1]), "+f"((d)[2]), "+f"((d)[3]) \
                 : "r"((a)[0]), "r"((a)[1]), "r"((a)[2]), "r"((a)[3]), \
                   "r"(b0), "r"(b1))

// ============================ prep kernel ============================
// One warp per row: fp32 -> bf16 + squared row norm. 20480 warps.
__global__ void prep_kernel(const float* __restrict__ feat, const float* __restrict__ cent) {
    int gw = (blockIdx.x * blockDim.x + threadIdx.x) >> 5;
    int lane = threadIdx.x & 31;
    if (gw >= B_ROWS + C_ROWS) return;

    const float* src;
    __nv_bfloat16* dst;
    float* nrm;
    if (gw < B_ROWS) {
        src = feat + (size_t)gw * DDIM;
        dst = g_feat_bf16 + (size_t)gw * DDIM;
        nrm = g_x2 + gw;
    } else {
        int r = gw - B_ROWS;
        src = cent + (size_t)r * DDIM;
        dst = g_cent_bf16 + (size_t)r * DDIM;
        nrm = g_c2 + r;
    }

    float s = 0.0f;
    #pragma unroll
    for (int i = 0; i < DDIM / 128; i++) {
        int idx = i * 128 + lane * 4;
        float4 v = *reinterpret_cast<const float4*>(src + idx);
        s = fmaf(v.x, v.x, s); s = fmaf(v.y, v.y, s);
        s = fmaf(v.z, v.z, s); s = fmaf(v.w, v.w, s);
        __nv_bfloat162 p0 = __floats2bfloat162_rn(v.x, v.y);
        __nv_bfloat162 p1 = __floats2bfloat162_rn(v.z, v.w);
        uint2 pk;
        pk.x = *reinterpret_cast<uint32_t*>(&p0);
        pk.y = *reinterpret_cast<uint32_t*>(&p1);
        *reinterpret_cast<uint2*>(dst + idx) = pk;
    }
    #pragma unroll
    for (int o = 16; o > 0; o >>= 1) s += __shfl_xor_sync(0xffffffffu, s, o);
    if (lane == 0) *nrm = s;
}

// ============================ GEMM kernel ============================
// CTA 128x128 output tile, 4 warps in 2(M) x 2(N), warp tile 64x64.
// 128 threads/CTA, 97KB smem/CTA -> 2 CTAs/SM.
// SMEM tiles K-major, 128B rows (TK=64 bf16), XOR-swizzled.
// 3-stage cp.async pipeline. Each k16 step is hand-interleaved into 8 groups
// of {1 LDSM (next-step frags) + <=1 cp.async (chunk kc+2) + 4 MMAs}: because
// every op is volatile asm, this source order IS the issue order, so the
// tensor pipe always has an MMA within a few slots and LDSM/LDGSTS latency
// hides under the MMA queue (the previous 8-LDSM bursts stalled both warps of
// an SMSP simultaneously). Chunk-boundary wait_group 0 + __syncthreads sits
// at the END of k16==2, when k16==3's fragments are already in registers.
// Hazards: buffer (kc+2)%3 writes start at chunk kc k16=0, after its last
// reads (as stage kc-1) completed before chunk kc-1's barrier (WAR safe);
// stage kc+1 fragment reads at k16==3 follow wait0+barrier (RAW safe).

// prologue-only: load one full stage at once (128 threads)
__device__ __forceinline__ void load_stage(uint32_t abuf, uint32_t bbuf,
                                           const __nv_bfloat16* Ag,
                                           const __nv_bfloat16* Bg,
                                           int kc, int tid) {
    #pragma unroll
    for (int i = 0; i < 8; i++) {            // A: 1024 granules / 128 threads
        int g = i * 128 + tid;
        int row = g >> 3, c = g & 7;
        uint32_t sm = abuf + row * 128 + ((c ^ (row & 7)) << 4);
        const void* gp = Ag + (size_t)row * DDIM + kc * TK + c * 8;
        CP_ASYNC16(sm, gp);
    }
    #pragma unroll
    for (int i = 0; i < 8; i++) {            // B: 1024 granules
        int g = i * 128 + tid;
        int row = g >> 3, c = g & 7;
        uint32_t sm = bbuf + row * 128 + ((c ^ (row & 7)) << 4);
        const void* gp = Bg + (size_t)row * DDIM + kc * TK + c * 8;
        CP_ASYNC16(sm, gp);
    }
}

// burst fragment load (bootstrap only)
#define LOAD_FRAGS(buf, stage_addr, k16_) do {                                   \
    uint32_t a_base_ = (stage_addr) + (warp_m * 64 + a_row) * 128;               \
    uint32_t b_base_ = (stage_addr) + A_STAGE_BYTES + (warp_n * 64 + b_row) * 128; \
    _Pragma("unroll")                                                            \
    for (int mi_ = 0; mi_ < 4; mi_++) {                                          \
        uint32_t ad_ = a_base_ + mi_ * (16 * 128) + ((((k16_) * 2 + a_kb) ^ arx) << 4); \
        LDSM_X4(af[buf][mi_], ad_);                                              \
    }                                                                            \
    _Pragma("unroll")                                                            \
    for (int ng_ = 0; ng_ < 4; ng_++) {                                          \
        uint32_t bd_ = b_base_ + ng_ * (16 * 128) + ((((k16_) * 2 + b_kb) ^ brx) << 4); \
        LDSM_X4(bf[buf][ng_], bd_);                                              \
    }                                                                            \
} while (0)

__global__ __launch_bounds__(128, 2) void gemm_kernel(float* __restrict__ out) {
    extern __shared__ char smem_raw[];
    uint32_t sb0 = smem_u32(smem_raw);
    uint32_t sb = (sb0 + 1023u) & ~1023u;    // 1024-align tile base

    int tid = threadIdx.x;
    int lane = tid & 31;
    int wid = tid >> 5;
    int warp_m = wid & 1;                    // 0..1
    int warp_n = wid >> 1;                   // 0..1

    // ldmatrix per-lane row/k-half selection
    int a_row = (lane & 7) + ((lane >> 3) & 1) * 8;   // mats: r0-7/k0, r8-15/k0, r0-7/k8, r8-15/k8
    int a_kb  = (lane >> 4) & 1;
    int b_row = (lane & 7) + ((lane >> 4) & 1) * 8;   // mats: n0-7/k0, n0-7/k8, n8-15/k0, n8-15/k8
    int b_kb  = (lane >> 3) & 1;
    int arx = a_row & 7;
    int brx = b_row & 7;

    float acc[4][8][4];
    #pragma unroll
    for (int mi = 0; mi < 4; mi++)
        #pragma unroll
        for (int ni = 0; ni < 8; ni++)
            #pragma unroll
            for (int j = 0; j < 4; j++) acc[mi][ni][j] = 0.0f;

    uint32_t af[2][4][4];
    uint32_t bf[2][4][4];   // [buf][ng]: {b0,b1} of n-tile 2ng, {b0,b1} of 2ng+1

    const __nv_bfloat16* Ag = g_feat_bf16 + (size_t)blockIdx.y * TM * DDIM;
    const __nv_bfloat16* Bg = g_cent_bf16 + (size_t)blockIdx.x * TN * DDIM;

    // prologue: stages 0,1
    #pragma unroll
    for (int s = 0; s < NSTAGE - 1; s++) {
        uint32_t ab = sb + s * STAGE_BYTES;
        load_stage(ab, ab + A_STAGE_BYTES, Ag, Bg, s, tid);
        CP_ASYNC_COMMIT();
    }
    CP_ASYNC_WAIT1();         // stage 0 complete (stage 1's group may be in flight)
    __syncthreads();          // stage 0 visible CTA-wide

    // per-thread granule coordinates for the interleaved next-stage loads:
    // per k16 step this thread issues 2 A granules + 2 B granules.
    int l_row = tid >> 3;                    // 0..15
    int l_c   = tid & 7;
    uint32_t l_sw = ((uint32_t)(l_c ^ (l_row & 7))) << 4;   // row%8 == l_row%8 (16-row groups)

    int pb = 0;
    LOAD_FRAGS(0, sb, 0);     // bootstrap frags(chunk0, k16=0) — only exposed burst

    for (int kc = 0; kc < KCHUNKS; kc++) {
        uint32_t cbuf = sb + (kc % NSTAGE) * STAGE_BYTES;
        uint32_t nbuf = sb + ((kc + 1) % NSTAGE) * STAGE_BYTES;
        int lkc = kc + 2;
        bool do_load = (lkc < KCHUNKS);
        uint32_t lbuf = sb + (lkc % NSTAGE) * STAGE_BYTES;

        #pragma unroll
        for (int k16 = 0; k16 < K16S; k16++) {
            int cur = pb, nxt = pb ^ 1;
            // select LDSM source for next-step fragments
            bool do_ldsm = (k16 < K16S - 1) || (kc + 1 < KCHUNKS);
            uint32_t ls_stage = (k16 < K16S - 1) ? cbuf : nbuf;
            int ls_k = (k16 < K16S - 1) ? (k16 + 1) : 0;
            uint32_t ls_abase = ls_stage + (warp_m * 64 + a_row) * 128;
            uint32_t ls_bbase = ls_stage + A_STAGE_BYTES + (warp_n * 64 + b_row) * 128;
            uint32_t ls_aoff = (((ls_k * 2 + a_kb) ^ arx) << 4);
            uint32_t ls_boff = (((ls_k * 2 + b_kb) ^ brx) << 4);

            // 8 interleaved groups: {1 LDSM + <=1 cp.async + 4 MMAs}
            #pragma unroll
            for (int g = 0; g < 8; g++) {
                if (do_ldsm) {
                    if (g < 4) {
                        LDSM_X4(af[nxt][g], ls_abase + g * (16 * 128) + ls_aoff);
                    } else {
                        LDSM_X4(bf[nxt][g - 4], ls_bbase + (g - 4) * (16 * 128) + ls_boff);
                    }
                }
                if (do_load && g < 4) {
                    int j = g >> 1;
                    int row = (k16 * 2 + j) * 16 + l_row;
                    if ((g & 1) == 0) {
                        CP_ASYNC16(lbuf + row * 128 + l_sw,
                                   Ag + (size_t)row * DDIM + lkc * TK + l_c * 8);
                    } else {
                        CP_ASYNC16(lbuf + A_STAGE_BYTES + row * 128 + l_sw,
                                   Bg + (size_t)row * DDIM + lkc * TK + l_c * 8);
                    }
                }
                int mi = g >> 1, nb = (g & 1) * 4;
                #pragma unroll
                for (int ni = nb; ni < nb + 4; ni++)
                    MMA_BF16(acc[mi][ni], af[cur][mi], bf[cur][ni >> 1][(ni & 1) * 2],
                             bf[cur][ni >> 1][(ni & 1) * 2 + 1]);
            }

            // chunk-boundary sync at END of k16==2: k16==3 frags already in regs,
            // so every warp resumes MMAs immediately after the barrier.
            if (k16 == K16S - 2) {
                CP_ASYNC_WAIT0();      // group(kc+1) — committed a full chunk ago
                __syncthreads();       // stage kc+1 visible; buffer (kc+2)%3 free
            }
            pb ^= 1;
        }
        CP_ASYNC_COMMIT();        // one group per chunk (empty in tail)
    }

    // ---------------- epilogue: dist = x2 + c2 - 2*acc ----------------
    int qid = lane >> 2;          // 0..7 row-in-8
    int tig = lane & 3;           // 0..3 col pair
    int row_base = blockIdx.y * TM + warp_m * 64;
    int col_base = blockIdx.x * TN + warp_n * 64;

    #pragma unroll
    for (int mi = 0; mi < 4; mi++) {
        int r0 = row_base + mi * 16 + qid;
        float x2a = __ldg(&g_x2[r0]);
        float x2b = __ldg(&g_x2[r0 + 8]);
        float* o0 = out + (size_t)r0 * C_ROWS;
        float* o1 = out + (size_t)(r0 + 8) * C_ROWS;
        #pragma unroll
        for (int ni = 0; ni < 8; ni++) {
            int c = col_base + ni * 8 + tig * 2;
            float c2x = __ldg(&g_c2[c]);
            float c2y = __ldg(&g_c2[c + 1]);
            float2 v0, v1;
            v0.x = fmaf(-2.0f, acc[mi][ni][0], x2a + c2x);
            v0.y = fmaf(-2.0f, acc[mi][ni][1], x2a + c2y);
            v1.x = fmaf(-2.0f, acc[mi][ni][2], x2b + c2x);
            v1.y = fmaf(-2.0f, acc[mi][ni][3], x2b + c2y);
            *reinterpret_cast<float2*>(o0 + c) = v0;
            *reinterpret_cast<float2*>(o1 + c) = v1;
        }
    }
}

// ============================ launch ============================
extern "C" void kernel_launch(void* const* d_in, const int* in_sizes, int n_in,
                              void* d_out, int out_size) {
    const float* feat = (const float*)d_in[0];
    const float* cent = (const float*)d_in[1];
    float* out = (float*)d_out;

    int nwarps = B_ROWS + C_ROWS;
    prep_kernel<<<(nwarps + 7) / 8, 256>>>(feat, cent);

    cudaFuncSetAttribute(gemm_kernel, cudaFuncAttributeMaxDynamicSharedMemorySize, SMEM_DYN);
    dim3 grid(C_ROWS / TN, B_ROWS / TM);   // (32, 128): x fastest -> wave shares B panel in L2
    gemm_kernel<<<grid, 128, SMEM_DYN>>>(out);
}

// round 15
// speedup vs baseline: 1.0181x; 1.0181x over previous
#include <cuda_runtime.h>
#include <cuda_bf16.h>
#include <cstdint>

#define B_ROWS 16384
#define C_ROWS 4096
#define DDIM   1024

// GEMM tiling
#define TM 128            // CTA M
#define TN 128            // CTA N
#define TK 64             // K chunk (per pipeline stage)
#define NSTAGE 3
#define KCHUNKS (DDIM / TK)        // 16
#define K16S (TK / 16)             // 4 mma k-steps per chunk

#define A_STAGE_BYTES (TM * TK * 2)            // 16384
#define B_STAGE_BYTES (TN * TK * 2)            // 16384
#define STAGE_BYTES (A_STAGE_BYTES + B_STAGE_BYTES)   // 32768
#define SMEM_DYN (1024 + NSTAGE * STAGE_BYTES)        // 99328  -> 2 CTAs/SM

// ---- device scratch (allocation-free rule: __device__ globals) ----
__device__ __align__(16) __nv_bfloat16 g_feat_bf16[B_ROWS * DDIM];   // 32 MB
__device__ __align__(16) __nv_bfloat16 g_cent_bf16[C_ROWS * DDIM];   // 8 MB
__device__ float g_x2[B_ROWS];
__device__ float g_c2[C_ROWS];

// ============================ PTX helpers (baseline PTX only) ============================
__device__ __forceinline__ uint32_t smem_u32(const void* p) {
    return (uint32_t)__cvta_generic_to_shared(p);
}

#define CP_ASYNC16(smem_addr, gptr) \
    asm volatile("cp.async.cg.shared.global [%0], [%1], 16;" \
                 :: "r"((uint32_t)(smem_addr)), "l"(gptr) : "memory")

#define CP_ASYNC_COMMIT() asm volatile("cp.async.commit_group;" ::: "memory")
#define CP_ASYNC_WAIT1()  asm volatile("cp.async.wait_group 1;" ::: "memory")
#define CP_ASYNC_WAIT0()  asm volatile("cp.async.wait_group 0;" ::: "memory")

#define LDSM_X4(r, addr) \
    asm volatile("ldmatrix.sync.aligned.m8n8.x4.shared.b16 {%0,%1,%2,%3}, [%4];" \
                 : "=r"((r)[0]), "=r"((r)[1]), "=r"((r)[2]), "=r"((r)[3]) \
                 : "r"((uint32_t)(addr)))

#define MMA_BF16(d, a, b0, b1) \
    asm volatile("mma.sync.aligned.m16n8k16.row.col.f32.bf16.bf16.f32 " \
                 "{%0,%1,%2,%3}, {%4,%5,%6,%7}, {%8,%9}, {%0,%1,%2,%3};" \
                 : "+f"((d)[0]), "+f"((d)[1]), "+f"((d)[2]), "+f"((d)[3]) \
                 : "r"((a)[0]), "r"((a)[1]), "r"((a)[2]), "r"((a)[3]), \
                   "r"(b0), "r"(b1))

// ============================ prep kernel ============================
// One warp per row: fp32 -> bf16 + squared row norm. 20480 warps.
__global__ void prep_kernel(const float* __restrict__ feat, const float* __restrict__ cent) {
    int gw = (blockIdx.x * blockDim.x + threadIdx.x) >> 5;
    int lane = threadIdx.x & 31;
    if (gw >= B_ROWS + C_ROWS) return;

    const float* src;
    __nv_bfloat16* dst;
    float* nrm;
    if (gw < B_ROWS) {
        src = feat + (size_t)gw * DDIM;
        dst = g_feat_bf16 + (size_t)gw * DDIM;
        nrm = g_x2 + gw;
    } else {
        int r = gw - B_ROWS;
        src = cent + (size_t)r * DDIM;
        dst = g_cent_bf16 + (size_t)r * DDIM;
        nrm = g_c2 + r;
    }

    float s = 0.0f;
    #pragma unroll
    for (int i = 0; i < DDIM / 128; i++) {
        int idx = i * 128 + lane * 4;
        float4 v = *reinterpret_cast<const float4*>(src + idx);
        s = fmaf(v.x, v.x, s); s = fmaf(v.y, v.y, s);
        s = fmaf(v.z, v.z, s); s = fmaf(v.w, v.w, s);
        __nv_bfloat162 p0 = __floats2bfloat162_rn(v.x, v.y);
        __nv_bfloat162 p1 = __floats2bfloat162_rn(v.z, v.w);
        uint2 pk;
        pk.x = *reinterpret_cast<uint32_t*>(&p0);
        pk.y = *reinterpret_cast<uint32_t*>(&p1);
        *reinterpret_cast<uint2*>(dst + idx) = pk;
    }
    #pragma unroll
    for (int o = 16; o > 0; o >>= 1) s += __shfl_xor_sync(0xffffffffu, s, o);
    if (lane == 0) *nrm = s;
}

// ============================ GEMM kernel ============================
// R12 structure (best: 302.6us, tensor 75.4%) + CTA phase offset.
// CTA 128x128 output tile, 4 warps in 2(M) x 2(N), warp tile 64x64.
// 128 threads/CTA, 97KB smem/CTA -> 2 CTAs/SM.
// 3-stage cp.async pipeline with MID-CHUNK synchronization (wait0+bar between
// k16==2 and k16==3, when k16==3's frags are already in registers).
// NEW: odd-parity CTAs nanosleep ~400ns (half a chunk period) after their
// prologue cp.asyncs are in flight, so the two co-resident CTAs' barrier
// windows interleave instead of phase-locking -> each CTA's warps cover the
// other's collective stalls.

// prologue-only: load one full stage at once (128 threads)
__device__ __forceinline__ void load_stage(uint32_t abuf, uint32_t bbuf,
                                           const __nv_bfloat16* Ag,
                                           const __nv_bfloat16* Bg,
                                           int kc, int tid) {
    #pragma unroll
    for (int i = 0; i < 8; i++) {            // A: 1024 granules / 128 threads
        int g = i * 128 + tid;
        int row = g >> 3, c = g & 7;
        uint32_t sm = abuf + row * 128 + ((c ^ (row & 7)) << 4);
        const void* gp = Ag + (size_t)row * DDIM + kc * TK + c * 8;
        CP_ASYNC16(sm, gp);
    }
    #pragma unroll
    for (int i = 0; i < 8; i++) {            // B: 1024 granules
        int g = i * 128 + tid;
        int row = g >> 3, c = g & 7;
        uint32_t sm = bbuf + row * 128 + ((c ^ (row & 7)) << 4);
        const void* gp = Bg + (size_t)row * DDIM + kc * TK + c * 8;
        CP_ASYNC16(sm, gp);
    }
}

// load af[buf]/bf[buf] fragments for one k16 step from a given stage
#define LOAD_FRAGS(buf, stage_addr, k16_) do {                                   \
    uint32_t a_base_ = (stage_addr) + (warp_m * 64 + a_row) * 128;               \
    uint32_t b_base_ = (stage_addr) + A_STAGE_BYTES + (warp_n * 64 + b_row) * 128; \
    _Pragma("unroll")                                                            \
    for (int mi_ = 0; mi_ < 4; mi_++) {                                          \
        uint32_t ad_ = a_base_ + mi_ * (16 * 128) + ((((k16_) * 2 + a_kb) ^ arx) << 4); \
        LDSM_X4(af[buf][mi_], ad_);                                              \
    }                                                                            \
    _Pragma("unroll")                                                            \
    for (int ng_ = 0; ng_ < 4; ng_++) {                                          \
        uint32_t bd_ = b_base_ + ng_ * (16 * 128) + ((((k16_) * 2 + b_kb) ^ brx) << 4); \
        LDSM_X4(bf[buf][ng_], bd_);                                              \
    }                                                                            \
} while (0)

__global__ __launch_bounds__(128, 2) void gemm_kernel(float* __restrict__ out) {
    extern __shared__ char smem_raw[];
    uint32_t sb0 = smem_u32(smem_raw);
    uint32_t sb = (sb0 + 1023u) & ~1023u;    // 1024-align tile base

    int tid = threadIdx.x;
    int lane = tid & 31;
    int wid = tid >> 5;
    int warp_m = wid & 1;                    // 0..1
    int warp_n = wid >> 1;                   // 0..1

    // ldmatrix per-lane row/k-half selection
    int a_row = (lane & 7) + ((lane >> 3) & 1) * 8;   // mats: r0-7/k0, r8-15/k0, r0-7/k8, r8-15/k8
    int a_kb  = (lane >> 4) & 1;
    int b_row = (lane & 7) + ((lane >> 4) & 1) * 8;   // mats: n0-7/k0, n0-7/k8, n8-15/k0, n8-15/k8
    int b_kb  = (lane >> 3) & 1;
    int arx = a_row & 7;
    int brx = b_row & 7;

    float acc[4][8][4];
    #pragma unroll
    for (int mi = 0; mi < 4; mi++)
        #pragma unroll
        for (int ni = 0; ni < 8; ni++)
            #pragma unroll
            for (int j = 0; j < 4; j++) acc[mi][ni][j] = 0.0f;

    uint32_t af[2][4][4];
    uint32_t bf[2][4][4];   // [buf][ng]: {b0,b1} of n-tile 2ng, {b0,b1} of 2ng+1

    const __nv_bfloat16* Ag = g_feat_bf16 + (size_t)blockIdx.y * TM * DDIM;
    const __nv_bfloat16* Bg = g_cent_bf16 + (size_t)blockIdx.x * TN * DDIM;

    // prologue: stages 0,1
    #pragma unroll
    for (int s = 0; s < NSTAGE - 1; s++) {
        uint32_t ab = sb + s * STAGE_BYTES;
        load_stage(ab, ab + A_STAGE_BYTES, Ag, Bg, s, tid);
        CP_ASYNC_COMMIT();
    }

    // phase offset: odd-parity CTAs sleep ~half a chunk period while their
    // prologue loads are in flight, desynchronizing co-resident CTA barriers.
    if (((blockIdx.x ^ blockIdx.y) & 1) != 0) __nanosleep(400);

    CP_ASYNC_WAIT1();         // stage 0 complete (stage 1's group may be in flight)
    __syncthreads();          // stage 0 visible CTA-wide

    // per-thread granule coordinates for the interleaved next-stage loads:
    // per k16 step this thread issues 2 A granules + 2 B granules.
    int l_row = tid >> 3;                    // 0..15
    int l_c   = tid & 7;
    uint32_t l_sw = ((uint32_t)(l_c ^ (l_row & 7))) << 4;   // row%8 == l_row%8 (16-row groups)

    int pb = 0;
    LOAD_FRAGS(0, sb, 0);     // bootstrap frags(chunk0, k16=0) — only exposed LDSM

    for (int kc = 0; kc < KCHUNKS; kc++) {
        uint32_t cbuf = sb + (kc % NSTAGE) * STAGE_BYTES;
        uint32_t nbuf = sb + ((kc + 1) % NSTAGE) * STAGE_BYTES;
        int lkc = kc + 2;
        bool do_load = (lkc < KCHUNKS);
        uint32_t lbuf = sb + (lkc % NSTAGE) * STAGE_BYTES;

        #pragma unroll
        for (int k16 = 0; k16 < K16S; k16++) {
            int cur = pb, nxt = pb ^ 1;
            // intra-chunk fragment prefetch (k16 0..2)
            if (k16 < K16S - 1) LOAD_FRAGS(nxt, cbuf, k16 + 1);
            // interleaved slice of chunk kc+2 loads: 2 A + 2 B granules
            if (do_load) {
                #pragma unroll
                for (int j = 0; j < 2; j++) {
                    int row = (k16 * 2 + j) * 16 + l_row;
                    uint32_t sma = lbuf + row * 128 + l_sw;
                    CP_ASYNC16(sma, Ag + (size_t)row * DDIM + lkc * TK + l_c * 8);
                    uint32_t smb = lbuf + A_STAGE_BYTES + row * 128 + l_sw;
                    CP_ASYNC16(smb, Bg + (size_t)row * DDIM + lkc * TK + l_c * 8);
                }
            }
            // mid-chunk sync: frags(kc,3) already in regs; next MMAs ready to go
            if (k16 == K16S - 2) {
                CP_ASYNC_WAIT0();      // group(kc+1) — committed a full chunk ago
                __syncthreads();       // stage kc+1 visible; buffer (kc+2)%3 free
            }
            // cross-chunk fragment prefetch from the now-resident next stage
            if (k16 == K16S - 1 && kc + 1 < KCHUNKS) LOAD_FRAGS(nxt, nbuf, 0);

            #pragma unroll
            for (int mi = 0; mi < 4; mi++)
                #pragma unroll
                for (int ni = 0; ni < 8; ni++)
                    MMA_BF16(acc[mi][ni], af[cur][mi], bf[cur][ni >> 1][(ni & 1) * 2],
                             bf[cur][ni >> 1][(ni & 1) * 2 + 1]);
            pb ^= 1;
        }
        CP_ASYNC_COMMIT();        // one group per chunk (empty in tail)
    }

    // ---------------- epilogue: dist = x2 + c2 - 2*acc ----------------
    int qid = lane >> 2;          // 0..7 row-in-8
    int tig = lane & 3;           // 0..3 col pair
    int row_base = blockIdx.y * TM + warp_m * 64;
    int col_base = blockIdx.x * TN + warp_n * 64;

    #pragma unroll
    for (int mi = 0; mi < 4; mi++) {
        int r0 = row_base + mi * 16 + qid;
        float x2a = __ldg(&g_x2[r0]);
        float x2b = __ldg(&g_x2[r0 + 8]);
        float* o0 = out + (size_t)r0 * C_ROWS;
        float* o1 = out + (size_t)(r0 + 8) * C_ROWS;
        #pragma unroll
        for (int ni = 0; ni < 8; ni++) {
            int c = col_base + ni * 8 + tig * 2;
            float c2x = __ldg(&g_c2[c]);
            float c2y = __ldg(&g_c2[c + 1]);
            float2 v0, v1;
            v0.x = fmaf(-2.0f, acc[mi][ni][0], x2a + c2x);
            v0.y = fmaf(-2.0f, acc[mi][ni][1], x2a + c2y);
            v1.x = fmaf(-2.0f, acc[mi][ni][2], x2b + c2x);
            v1.y = fmaf(-2.0f, acc[mi][ni][3], x2b + c2y);
            *reinterpret_cast<float2*>(o0 + c) = v0;
            *reinterpret_cast<float2*>(o1 + c) = v1;
        }
    }
}

// ============================ launch ============================
extern "C" void kernel_launch(void* const* d_in, const int* in_sizes, int n_in,
                              void* d_out, int out_size) {
    const float* feat = (const float*)d_in[0];
    const float* cent = (const float*)d_in[1];
    float* out = (float*)d_out;

    int nwarps = B_ROWS + C_ROWS;
    prep_kernel<<<(nwarps + 7) / 8, 256>>>(feat, cent);

    cudaFuncSetAttribute(gemm_kernel, cudaFuncAttributeMaxDynamicSharedMemorySize, SMEM_DYN);
    dim3 grid(C_ROWS / TN, B_ROWS / TM);   // (32, 128): x fastest -> wave shares B panel in L2
    gemm_kernel<<<grid, 128, SMEM_DYN>>>(out);
}

// round 16
// speedup vs baseline: 1.0321x; 1.0137x over previous
#include <cuda_runtime.h>
#include <cuda_bf16.h>
#include <cstdint>

#define B_ROWS 16384
#define C_ROWS 4096
#define DDIM   1024

// GEMM tiling
#define TM 128            // CTA M
#define TN 128            // CTA N
#define TK 64             // K chunk (per pipeline stage)
#define NSTAGE 3
#define KCHUNKS (DDIM / TK)        // 16
#define K16S (TK / 16)             // 4 mma k-steps per chunk

#define A_STAGE_BYTES (TM * TK * 2)            // 16384
#define B_STAGE_BYTES (TN * TK * 2)            // 16384
#define STAGE_BYTES (A_STAGE_BYTES + B_STAGE_BYTES)   // 32768
#define SMEM_DYN (1024 + NSTAGE * STAGE_BYTES)        // 99328  -> 2 CTAs/SM

// ---- device scratch (allocation-free rule: __device__ globals) ----
__device__ __align__(16) __nv_bfloat16 g_feat_bf16[B_ROWS * DDIM];   // 32 MB
__device__ __align__(16) __nv_bfloat16 g_cent_bf16[C_ROWS * DDIM];   // 8 MB
__device__ float g_x2[B_ROWS];
__device__ float g_c2[C_ROWS];

// ============================ PTX helpers (baseline PTX only) ============================
__device__ __forceinline__ uint32_t smem_u32(const void* p) {
    return (uint32_t)__cvta_generic_to_shared(p);
}

#define CP_ASYNC16(smem_addr, gptr) \
    asm volatile("cp.async.cg.shared.global [%0], [%1], 16;" \
                 :: "r"((uint32_t)(smem_addr)), "l"(gptr) : "memory")

#define CP_ASYNC_COMMIT() asm volatile("cp.async.commit_group;" ::: "memory")
#define CP_ASYNC_WAIT1()  asm volatile("cp.async.wait_group 1;" ::: "memory")

#define LDSM_X4(r, addr) \
    asm volatile("ldmatrix.sync.aligned.m8n8.x4.shared.b16 {%0,%1,%2,%3}, [%4];" \
                 : "=r"((r)[0]), "=r"((r)[1]), "=r"((r)[2]), "=r"((r)[3]) \
                 : "r"((uint32_t)(addr)))

#define MMA_BF16(d, a, b0, b1) \
    asm volatile("mma.sync.aligned.m16n8k16.row.col.f32.bf16.bf16.f32 " \
                 "{%0,%1,%2,%3}, {%4,%5,%6,%7}, {%8,%9}, {%0,%1,%2,%3};" \
                 : "+f"((d)[0]), "+f"((d)[1]), "+f"((d)[2]), "+f"((d)[3]) \
                 : "r"((a)[0]), "r"((a)[1]), "r"((a)[2]), "r"((a)[3]), \
                   "r"(b0), "r"(b1))

// ============================ prep kernel ============================
// One warp per row: fp32 -> bf16 + squared row norm. 20480 warps.
__global__ void prep_kernel(const float* __restrict__ feat, const float* __restrict__ cent) {
    int gw = (blockIdx.x * blockDim.x + threadIdx.x) >> 5;
    int lane = threadIdx.x & 31;
    if (gw >= B_ROWS + C_ROWS) return;

    const float* src;
    __nv_bfloat16* dst;
    float* nrm;
    if (gw < B_ROWS) {
        src = feat + (size_t)gw * DDIM;
        dst = g_feat_bf16 + (size_t)gw * DDIM;
        nrm = g_x2 + gw;
    } else {
        int r = gw - B_ROWS;
        src = cent + (size_t)r * DDIM;
        dst = g_cent_bf16 + (size_t)r * DDIM;
        nrm = g_c2 + r;
    }

    float s = 0.0f;
    #pragma unroll
    for (int i = 0; i < DDIM / 128; i++) {
        int idx = i * 128 + lane * 4;
        float4 v = *reinterpret_cast<const float4*>(src + idx);
        s = fmaf(v.x, v.x, s); s = fmaf(v.y, v.y, s);
        s = fmaf(v.z, v.z, s); s = fmaf(v.w, v.w, s);
        __nv_bfloat162 p0 = __floats2bfloat162_rn(v.x, v.y);
        __nv_bfloat162 p1 = __floats2bfloat162_rn(v.z, v.w);
        uint2 pk;
        pk.x = *reinterpret_cast<uint32_t*>(&p0);
        pk.y = *reinterpret_cast<uint32_t*>(&p1);
        *reinterpret_cast<uint2*>(dst + idx) = pk;
    }
    #pragma unroll
    for (int o = 16; o > 0; o >>= 1) s += __shfl_xor_sync(0xffffffffu, s, o);
    if (lane == 0) *nrm = s;
}

// ============================ GEMM kernel ============================
// CTA 128x128 output tile, 4 warps in 2(M) x 2(N), warp tile 64x64.
// 128 threads/CTA, 97KB smem/CTA -> 2 CTAs/SM.
// SMEM tiles K-major, 128B rows (TK=64 bf16), XOR-swizzled.
// 3-stage cp.async pipeline, mid-chunk synchronization, EARLY-COMMIT loads:
// all 16 granules for chunk kc+2 are issued during k16=0..1 and committed at
// the end of k16==1. The mid-chunk wait (end of k16==2) is wait_group 1 —
// it drains group(kc+1), whose cp.asyncs were issued ~5 k16-periods earlier
// (compared to ~3 with end-of-chunk commit), giving DRAM latency (~380-577
// cyc) comfortable slack so the wait doesn't block on memory completion.
// k16==3's fragments are already in registers at the barrier, and k16==3
// prefetches chunk kc+1's first fragments from the now-resident next stage.
// Hazards: buffer (kc+2)%3 writes start at chunk kc k16=0, after its last
// reads (as stage kc-1, k16==2 of chunk kc-1) which precede chunk kc-1's
// barrier (WAR safe); stage kc+1 reads at k16==3 follow wait1+barrier that
// drains group kc+1 (RAW safe). One commit per chunk (empty in tail).

// prologue-only: load one full stage at once (128 threads)
__device__ __forceinline__ void load_stage(uint32_t abuf, uint32_t bbuf,
                                           const __nv_bfloat16* Ag,
                                           const __nv_bfloat16* Bg,
                                           int kc, int tid) {
    #pragma unroll
    for (int i = 0; i < 8; i++) {            // A: 1024 granules / 128 threads
        int g = i * 128 + tid;
        int row = g >> 3, c = g & 7;
        uint32_t sm = abuf + row * 128 + ((c ^ (row & 7)) << 4);
        const void* gp = Ag + (size_t)row * DDIM + kc * TK + c * 8;
        CP_ASYNC16(sm, gp);
    }
    #pragma unroll
    for (int i = 0; i < 8; i++) {            // B: 1024 granules
        int g = i * 128 + tid;
        int row = g >> 3, c = g & 7;
        uint32_t sm = bbuf + row * 128 + ((c ^ (row & 7)) << 4);
        const void* gp = Bg + (size_t)row * DDIM + kc * TK + c * 8;
        CP_ASYNC16(sm, gp);
    }
}

// load af[buf]/bf[buf] fragments for one k16 step from a given stage
#define LOAD_FRAGS(buf, stage_addr, k16_) do {                                   \
    uint32_t a_base_ = (stage_addr) + (warp_m * 64 + a_row) * 128;               \
    uint32_t b_base_ = (stage_addr) + A_STAGE_BYTES + (warp_n * 64 + b_row) * 128; \
    _Pragma("unroll")                                                            \
    for (int mi_ = 0; mi_ < 4; mi_++) {                                          \
        uint32_t ad_ = a_base_ + mi_ * (16 * 128) + ((((k16_) * 2 + a_kb) ^ arx) << 4); \
        LDSM_X4(af[buf][mi_], ad_);                                              \
    }                                                                            \
    _Pragma("unroll")                                                            \
    for (int ng_ = 0; ng_ < 4; ng_++) {                                          \
        uint32_t bd_ = b_base_ + ng_ * (16 * 128) + ((((k16_) * 2 + b_kb) ^ brx) << 4); \
        LDSM_X4(bf[buf][ng_], bd_);                                              \
    }                                                                            \
} while (0)

__global__ __launch_bounds__(128, 2) void gemm_kernel(float* __restrict__ out) {
    extern __shared__ char smem_raw[];
    uint32_t sb0 = smem_u32(smem_raw);
    uint32_t sb = (sb0 + 1023u) & ~1023u;    // 1024-align tile base

    int tid = threadIdx.x;
    int lane = tid & 31;
    int wid = tid >> 5;
    int warp_m = wid & 1;                    // 0..1
    int warp_n = wid >> 1;                   // 0..1

    // ldmatrix per-lane row/k-half selection
    int a_row = (lane & 7) + ((lane >> 3) & 1) * 8;   // mats: r0-7/k0, r8-15/k0, r0-7/k8, r8-15/k8
    int a_kb  = (lane >> 4) & 1;
    int b_row = (lane & 7) + ((lane >> 4) & 1) * 8;   // mats: n0-7/k0, n0-7/k8, n8-15/k0, n8-15/k8
    int b_kb  = (lane >> 3) & 1;
    int arx = a_row & 7;
    int brx = b_row & 7;

    float acc[4][8][4];
    #pragma unroll
    for (int mi = 0; mi < 4; mi++)
        #pragma unroll
        for (int ni = 0; ni < 8; ni++)
            #pragma unroll
            for (int j = 0; j < 4; j++) acc[mi][ni][j] = 0.0f;

    uint32_t af[2][4][4];
    uint32_t bf[2][4][4];   // [buf][ng]: {b0,b1} of n-tile 2ng, {b0,b1} of 2ng+1

    const __nv_bfloat16* Ag = g_feat_bf16 + (size_t)blockIdx.y * TM * DDIM;
    const __nv_bfloat16* Bg = g_cent_bf16 + (size_t)blockIdx.x * TN * DDIM;

    // prologue: stages 0,1
    #pragma unroll
    for (int s = 0; s < NSTAGE - 1; s++) {
        uint32_t ab = sb + s * STAGE_BYTES;
        load_stage(ab, ab + A_STAGE_BYTES, Ag, Bg, s, tid);
        CP_ASYNC_COMMIT();
    }
    CP_ASYNC_WAIT1();         // stage 0 complete (stage 1's group may be in flight)
    __syncthreads();          // stage 0 visible CTA-wide

    // per-thread granule coordinates for the interleaved next-stage loads:
    // k16=0..1 only, 4 A granules + 4 B granules per step.
    int l_row = tid >> 3;                    // 0..15
    int l_c   = tid & 7;
    uint32_t l_sw = ((uint32_t)(l_c ^ (l_row & 7))) << 4;   // row%8 == l_row%8 (16-row groups)

    int pb = 0;
    LOAD_FRAGS(0, sb, 0);     // bootstrap frags(chunk0, k16=0) — only exposed LDSM

    for (int kc = 0; kc < KCHUNKS; kc++) {
        uint32_t cbuf = sb + (kc % NSTAGE) * STAGE_BYTES;
        uint32_t nbuf = sb + ((kc + 1) % NSTAGE) * STAGE_BYTES;
        int lkc = kc + 2;
        bool do_load = (lkc < KCHUNKS);
        uint32_t lbuf = sb + (lkc % NSTAGE) * STAGE_BYTES;

        #pragma unroll
        for (int k16 = 0; k16 < K16S; k16++) {
            int cur = pb, nxt = pb ^ 1;
            // intra-chunk fragment prefetch (k16 0..2)
            if (k16 < K16S - 1) LOAD_FRAGS(nxt, cbuf, k16 + 1);
            // chunk kc+2 loads, front-loaded into k16=0..1: 4 A + 4 B granules
            if (do_load && k16 < 2) {
                #pragma unroll
                for (int j = 0; j < 4; j++) {
                    int row = k16 * 64 + j * 16 + l_row;
                    uint32_t sma = lbuf + row * 128 + l_sw;
                    CP_ASYNC16(sma, Ag + (size_t)row * DDIM + lkc * TK + l_c * 8);
                    uint32_t smb = lbuf + A_STAGE_BYTES + row * 128 + l_sw;
                    CP_ASYNC16(smb, Bg + (size_t)row * DDIM + lkc * TK + l_c * 8);
                }
            }
            // early commit of chunk kc+2's group (empty in tail; 1 per chunk)
            if (k16 == 1) CP_ASYNC_COMMIT();
            // mid-chunk sync: frags(kc,3) already in regs; wait1 drains
            // group(kc+1) (issued ~5 k16-periods ago), leaves kc+2 in flight
            if (k16 == K16S - 2) {
                CP_ASYNC_WAIT1();
                __syncthreads();       // stage kc+1 visible; buffer (kc+2)%3 free
            }
            // cross-chunk fragment prefetch from the now-resident next stage
            if (k16 == K16S - 1 && kc + 1 < KCHUNKS) LOAD_FRAGS(nxt, nbuf, 0);

            #pragma unroll
            for (int mi = 0; mi < 4; mi++)
                #pragma unroll
                for (int ni = 0; ni < 8; ni++)
                    MMA_BF16(acc[mi][ni], af[cur][mi], bf[cur][ni >> 1][(ni & 1) * 2],
                             bf[cur][ni >> 1][(ni & 1) * 2 + 1]);
            pb ^= 1;
        }
    }

    // ---------------- epilogue: dist = x2 + c2 - 2*acc ----------------
    int qid = lane >> 2;          // 0..7 row-in-8
    int tig = lane & 3;           // 0..3 col pair
    int row_base = blockIdx.y * TM + warp_m * 64;
    int col_base = blockIdx.x * TN + warp_n * 64;

    #pragma unroll
    for (int mi = 0; mi < 4; mi++) {
        int r0 = row_base + mi * 16 + qid;
        float x2a = __ldg(&g_x2[r0]);
        float x2b = __ldg(&g_x2[r0 + 8]);
        float* o0 = out + (size_t)r0 * C_ROWS;
        float* o1 = out + (size_t)(r0 + 8) * C_ROWS;
        #pragma unroll
        for (int ni = 0; ni < 8; ni++) {
            int c = col_base + ni * 8 + tig * 2;
            float c2x = __ldg(&g_c2[c]);
            float c2y = __ldg(&g_c2[c + 1]);
            float2 v0, v1;
            v0.x = fmaf(-2.0f, acc[mi][ni][0], x2a + c2x);
            v0.y = fmaf(-2.0f, acc[mi][ni][1], x2a + c2y);
            v1.x = fmaf(-2.0f, acc[mi][ni][2], x2b + c2x);
            v1.y = fmaf(-2.0f, acc[mi][ni][3], x2b + c2y);
            *reinterpret_cast<float2*>(o0 + c) = v0;
            *reinterpret_cast<float2*>(o1 + c) = v1;
        }
    }
}

// ============================ launch ============================
extern "C" void kernel_launch(void* const* d_in, const int* in_sizes, int n_in,
                              void* d_out, int out_size) {
    const float* feat = (const float*)d_in[0];
    const float* cent = (const float*)d_in[1];
    float* out = (float*)d_out;

    int nwarps = B_ROWS + C_ROWS;
    prep_kernel<<<(nwarps + 7) / 8, 256>>>(feat, cent);

    cudaFuncSetAttribute(gemm_kernel, cudaFuncAttributeMaxDynamicSharedMemorySize, SMEM_DYN);
    dim3 grid(C_ROWS / TN, B_ROWS / TM);   // (32, 128): x fastest -> wave shares B panel in L2
    gemm_kernel<<<grid, 128, SMEM_DYN>>>(out);
}

// round 17
// speedup vs baseline: 1.0366x; 1.0045x over previous
#include <cuda_runtime.h>
#include <cuda_bf16.h>
#include <cstdint>

#define B_ROWS 16384
#define C_ROWS 4096
#define DDIM   1024

// GEMM tiling
#define TM 128            // CTA M
#define TN 128            // CTA N
#define TK 64             // K chunk (per pipeline stage)
#define NSTAGE 3
#define KCHUNKS (DDIM / TK)        // 16
#define K16S (TK / 16)             // 4 mma k-steps per chunk

#define A_STAGE_BYTES (TM * TK * 2)            // 16384
#define B_STAGE_BYTES (TN * TK * 2)            // 16384
#define STAGE_BYTES (A_STAGE_BYTES + B_STAGE_BYTES)   // 32768
#define SMEM_DYN (1024 + NSTAGE * STAGE_BYTES)        // 99328  -> 2 CTAs/SM

// ---- device scratch (allocation-free rule: __device__ globals) ----
__device__ __align__(16) __nv_bfloat16 g_feat_bf16[B_ROWS * DDIM];   // 32 MB
__device__ __align__(16) __nv_bfloat16 g_cent_bf16[C_ROWS * DDIM];   // 8 MB
__device__ float g_x2[B_ROWS];
__device__ float g_c2[C_ROWS];

// ============================ PTX helpers (baseline PTX only) ============================
__device__ __forceinline__ uint32_t smem_u32(const void* p) {
    return (uint32_t)__cvta_generic_to_shared(p);
}

#define CP_ASYNC16(smem_addr, gptr) \
    asm volatile("cp.async.cg.shared.global [%0], [%1], 16;" \
                 :: "r"((uint32_t)(smem_addr)), "l"(gptr) : "memory")

#define CP_ASYNC_COMMIT() asm volatile("cp.async.commit_group;" ::: "memory")
#define CP_ASYNC_WAIT1()  asm volatile("cp.async.wait_group 1;" ::: "memory")

#define LDSM_X4(r, addr) \
    asm volatile("ldmatrix.sync.aligned.m8n8.x4.shared.b16 {%0,%1,%2,%3}, [%4];" \
                 : "=r"((r)[0]), "=r"((r)[1]), "=r"((r)[2]), "=r"((r)[3]) \
                 : "r"((uint32_t)(addr)))

#define MMA_BF16(d, a, b0, b1) \
    asm volatile("mma.sync.aligned.m16n8k16.row.col.f32.bf16.bf16.f32 " \
                 "{%0,%1,%2,%3}, {%4,%5,%6,%7}, {%8,%9}, {%0,%1,%2,%3};" \
                 : "+f"((d)[0]), "+f"((d)[1]), "+f"((d)[2]), "+f"((d)[3]) \
                 : "r"((a)[0]), "r"((a)[1]), "r"((a)[2]), "r"((a)[3]), \
                   "r"(b0), "r"(b1))

// ============================ prep kernel ============================
// One warp per row: fp32 -> bf16 + squared row norm. 20480 warps.
__global__ void prep_kernel(const float* __restrict__ feat, const float* __restrict__ cent) {
    int gw = (blockIdx.x * blockDim.x + threadIdx.x) >> 5;
    int lane = threadIdx.x & 31;
    if (gw >= B_ROWS + C_ROWS) return;

    const float* src;
    __nv_bfloat16* dst;
    float* nrm;
    if (gw < B_ROWS) {
        src = feat + (size_t)gw * DDIM;
        dst = g_feat_bf16 + (size_t)gw * DDIM;
        nrm = g_x2 + gw;
    } else {
        int r = gw - B_ROWS;
        src = cent + (size_t)r * DDIM;
        dst = g_cent_bf16 + (size_t)r * DDIM;
        nrm = g_c2 + r;
    }

    float s = 0.0f;
    #pragma unroll
    for (int i = 0; i < DDIM / 128; i++) {
        int idx = i * 128 + lane * 4;
        float4 v = *reinterpret_cast<const float4*>(src + idx);
        s = fmaf(v.x, v.x, s); s = fmaf(v.y, v.y, s);
        s = fmaf(v.z, v.z, s); s = fmaf(v.w, v.w, s);
        __nv_bfloat162 p0 = __floats2bfloat162_rn(v.x, v.y);
        __nv_bfloat162 p1 = __floats2bfloat162_rn(v.z, v.w);
        uint2 pk;
        pk.x = *reinterpret_cast<uint32_t*>(&p0);
        pk.y = *reinterpret_cast<uint32_t*>(&p1);
        *reinterpret_cast<uint2*>(dst + idx) = pk;
    }
    #pragma unroll
    for (int o = 16; o > 0; o >>= 1) s += __shfl_xor_sync(0xffffffffu, s, o);
    if (lane == 0) *nrm = s;
}

// ============================ GEMM kernel ============================
// CTA 128x128 output tile, 4 warps in 2(M) x 2(N), warp tile 64x64.
// 128 threads/CTA, 97KB smem/CTA -> 2 CTAs/SM.
// SMEM tiles K-major, 128B rows (TK=64 bf16), XOR-swizzled.
// 3-stage cp.async pipeline, mid-chunk synchronization, MAX-SLACK loads:
// all 16 granules for chunk kc+2 issue in k16==0 and commit at its end.
// The mid-chunk wait (end of k16==2) is wait_group 1 — it drains group(kc+1),
// whose cp.asyncs were issued ~6 k16-periods earlier (~900+ cyc > DRAM
// latency), so the wait never blocks on memory completion. k16==3's
// fragments are already in registers at the barrier, and k16==3 prefetches
// chunk kc+1's first fragments from the now-resident next stage.
// Hazards: buffer (kc+2)%3 writes start at chunk kc k16=0, after its last
// reads (as stage kc-1, k16==2 of chunk kc-1) which precede chunk kc-1's
// barrier (WAR safe); stage kc+1 reads at k16==3 follow wait1+barrier that
// drains group kc+1 (RAW safe). One commit per chunk (empty in tail).

// prologue-only: load one full stage at once (128 threads)
__device__ __forceinline__ void load_stage(uint32_t abuf, uint32_t bbuf,
                                           const __nv_bfloat16* Ag,
                                           const __nv_bfloat16* Bg,
                                           int kc, int tid) {
    #pragma unroll
    for (int i = 0; i < 8; i++) {            // A: 1024 granules / 128 threads
        int g = i * 128 + tid;
        int row = g >> 3, c = g & 7;
        uint32_t sm = abuf + row * 128 + ((c ^ (row & 7)) << 4);
        const void* gp = Ag + (size_t)row * DDIM + kc * TK + c * 8;
        CP_ASYNC16(sm, gp);
    }
    #pragma unroll
    for (int i = 0; i < 8; i++) {            // B: 1024 granules
        int g = i * 128 + tid;
        int row = g >> 3, c = g & 7;
        uint32_t sm = bbuf + row * 128 + ((c ^ (row & 7)) << 4);
        const void* gp = Bg + (size_t)row * DDIM + kc * TK + c * 8;
        CP_ASYNC16(sm, gp);
    }
}

// load af[buf]/bf[buf] fragments for one k16 step from a given stage
#define LOAD_FRAGS(buf, stage_addr, k16_) do {                                   \
    uint32_t a_base_ = (stage_addr) + (warp_m * 64 + a_row) * 128;               \
    uint32_t b_base_ = (stage_addr) + A_STAGE_BYTES + (warp_n * 64 + b_row) * 128; \
    _Pragma("unroll")                                                            \
    for (int mi_ = 0; mi_ < 4; mi_++) {                                          \
        uint32_t ad_ = a_base_ + mi_ * (16 * 128) + ((((k16_) * 2 + a_kb) ^ arx) << 4); \
        LDSM_X4(af[buf][mi_], ad_);                                              \
    }                                                                            \
    _Pragma("unroll")                                                            \
    for (int ng_ = 0; ng_ < 4; ng_++) {                                          \
        uint32_t bd_ = b_base_ + ng_ * (16 * 128) + ((((k16_) * 2 + b_kb) ^ brx) << 4); \
        LDSM_X4(bf[buf][ng_], bd_);                                              \
    }                                                                            \
} while (0)

__global__ __launch_bounds__(128, 2) void gemm_kernel(float* __restrict__ out) {
    extern __shared__ char smem_raw[];
    uint32_t sb0 = smem_u32(smem_raw);
    uint32_t sb = (sb0 + 1023u) & ~1023u;    // 1024-align tile base

    int tid = threadIdx.x;
    int lane = tid & 31;
    int wid = tid >> 5;
    int warp_m = wid & 1;                    // 0..1
    int warp_n = wid >> 1;                   // 0..1

    // ldmatrix per-lane row/k-half selection
    int a_row = (lane & 7) + ((lane >> 3) & 1) * 8;   // mats: r0-7/k0, r8-15/k0, r0-7/k8, r8-15/k8
    int a_kb  = (lane >> 4) & 1;
    int b_row = (lane & 7) + ((lane >> 4) & 1) * 8;   // mats: n0-7/k0, n0-7/k8, n8-15/k0, n8-15/k8
    int b_kb  = (lane >> 3) & 1;
    int arx = a_row & 7;
    int brx = b_row & 7;

    float acc[4][8][4];
    #pragma unroll
    for (int mi = 0; mi < 4; mi++)
        #pragma unroll
        for (int ni = 0; ni < 8; ni++)
            #pragma unroll
            for (int j = 0; j < 4; j++) acc[mi][ni][j] = 0.0f;

    uint32_t af[2][4][4];
    uint32_t bf[2][4][4];   // [buf][ng]: {b0,b1} of n-tile 2ng, {b0,b1} of 2ng+1

    const __nv_bfloat16* Ag = g_feat_bf16 + (size_t)blockIdx.y * TM * DDIM;
    const __nv_bfloat16* Bg = g_cent_bf16 + (size_t)blockIdx.x * TN * DDIM;

    // prologue: stages 0,1
    #pragma unroll
    for (int s = 0; s < NSTAGE - 1; s++) {
        uint32_t ab = sb + s * STAGE_BYTES;
        load_stage(ab, ab + A_STAGE_BYTES, Ag, Bg, s, tid);
        CP_ASYNC_COMMIT();
    }
    CP_ASYNC_WAIT1();         // stage 0 complete (stage 1's group may be in flight)
    __syncthreads();          // stage 0 visible CTA-wide

    // per-thread granule coordinates for the k16==0 load burst (8 A + 8 B)
    int l_row = tid >> 3;                    // 0..15
    int l_c   = tid & 7;
    uint32_t l_sw = ((uint32_t)(l_c ^ (l_row & 7))) << 4;   // row%8 == l_row%8 (16-row groups)

    int pb = 0;
    LOAD_FRAGS(0, sb, 0);     // bootstrap frags(chunk0, k16=0) — only exposed LDSM

    for (int kc = 0; kc < KCHUNKS; kc++) {
        uint32_t cbuf = sb + (kc % NSTAGE) * STAGE_BYTES;
        uint32_t nbuf = sb + ((kc + 1) % NSTAGE) * STAGE_BYTES;
        int lkc = kc + 2;
        bool do_load = (lkc < KCHUNKS);
        uint32_t lbuf = sb + (lkc % NSTAGE) * STAGE_BYTES;

        #pragma unroll
        for (int k16 = 0; k16 < K16S; k16++) {
            int cur = pb, nxt = pb ^ 1;
            // intra-chunk fragment prefetch (k16 0..2)
            if (k16 < K16S - 1) LOAD_FRAGS(nxt, cbuf, k16 + 1);
            // chunk kc+2 loads: ALL 16 granules in k16==0 (max wait slack)
            if (do_load && k16 == 0) {
                #pragma unroll
                for (int j = 0; j < 8; j++) {
                    int row = j * 16 + l_row;
                    uint32_t sma = lbuf + row * 128 + l_sw;
                    CP_ASYNC16(sma, Ag + (size_t)row * DDIM + lkc * TK + l_c * 8);
                    uint32_t smb = lbuf + A_STAGE_BYTES + row * 128 + l_sw;
                    CP_ASYNC16(smb, Bg + (size_t)row * DDIM + lkc * TK + l_c * 8);
                }
            }
            // early commit of chunk kc+2's group (empty in tail; 1 per chunk)
            if (k16 == 0) CP_ASYNC_COMMIT();
            // mid-chunk sync: frags(kc,3) already in regs; wait1 drains
            // group(kc+1) (issued ~6 k16-periods ago), leaves kc+2 in flight
            if (k16 == K16S - 2) {
                CP_ASYNC_WAIT1();
                __syncthreads();       // stage kc+1 visible; buffer (kc+2)%3 free
            }
            // cross-chunk fragment prefetch from the now-resident next stage
            if (k16 == K16S - 1 && kc + 1 < KCHUNKS) LOAD_FRAGS(nxt, nbuf, 0);

            #pragma unroll
            for (int mi = 0; mi < 4; mi++)
                #pragma unroll
                for (int ni = 0; ni < 8; ni++)
                    MMA_BF16(acc[mi][ni], af[cur][mi], bf[cur][ni >> 1][(ni & 1) * 2],
                             bf[cur][ni >> 1][(ni & 1) * 2 + 1]);
            pb ^= 1;
        }
    }

    // ---------------- epilogue: dist = x2 + c2 - 2*acc ----------------
    int qid = lane >> 2;          // 0..7 row-in-8
    int tig = lane & 3;           // 0..3 col pair
    int row_base = blockIdx.y * TM + warp_m * 64;
    int col_base = blockIdx.x * TN + warp_n * 64;

    #pragma unroll
    for (int mi = 0; mi < 4; mi++) {
        int r0 = row_base + mi * 16 + qid;
        float x2a = __ldg(&g_x2[r0]);
        float x2b = __ldg(&g_x2[r0 + 8]);
        float* o0 = out + (size_t)r0 * C_ROWS;
        float* o1 = out + (size_t)(r0 + 8) * C_ROWS;
        #pragma unroll
        for (int ni = 0; ni < 8; ni++) {
            int c = col_base + ni * 8 + tig * 2;
            float c2x = __ldg(&g_c2[c]);
            float c2y = __ldg(&g_c2[c + 1]);
            float2 v0, v1;
            v0.x = fmaf(-2.0f, acc[mi][ni][0], x2a + c2x);
            v0.y = fmaf(-2.0f, acc[mi][ni][1], x2a + c2y);
            v1.x = fmaf(-2.0f, acc[mi][ni][2], x2b + c2x);
            v1.y = fmaf(-2.0f, acc[mi][ni][3], x2b + c2y);
            *reinterpret_cast<float2*>(o0 + c) = v0;
            *reinterpret_cast<float2*>(o1 + c) = v1;
        }
    }
}

// ============================ launch ============================
extern "C" void kernel_launch(void* const* d_in, const int* in_sizes, int n_in,
                              void* d_out, int out_size) {
    const float* feat = (const float*)d_in[0];
    const float* cent = (const float*)d_in[1];
    float* out = (float*)d_out;

    int nwarps = B_ROWS + C_ROWS;
    prep_kernel<<<(nwarps + 7) / 8, 256>>>(feat, cent);

    cudaFuncSetAttribute(gemm_kernel, cudaFuncAttributeMaxDynamicSharedMemorySize, SMEM_DYN);
    dim3 grid(C_ROWS / TN, B_ROWS / TM);   // (32, 128): x fastest -> wave shares B panel in L2
    gemm_kernel<<<grid, 128, SMEM_DYN>>>(out);
}